// round 15
// baseline (speedup 1.0000x reference)
#include <cuda_runtime.h>
#include <cuda_fp16.h>
#include <math_constants.h>
#include <mma.h>

using namespace nvcuda;

#define D 128
#define NEG_SLOPE 0.2f
#define EPS_DEN 1e-16f

#define N_MAX 50048
#define DEG_MAX 192      // >> max expected degree (~60 for this dist)

#define TK 32
#define LDA (TK + 4)
#define LDB (D + 4)

// ---- static scratch (no device allocations allowed) ----
__device__ __align__(16) float  g_h[N_MAX * D];          // projected features (fp32)
__device__ __align__(16) __half g_hh[N_MAX * D];         // fp16 mirror for gather
__device__ __align__(16) float g_ws[D];                  // W @ att_src
__device__ __align__(16) float g_wd[D];                  // W @ att_dst
__device__ float g_asrc[N_MAX];
__device__ float g_adst[N_MAX];
__device__ int   g_cursor[N_MAX];                        // per-dst cursor == degree
__device__ __align__(16) int   g_esrc[N_MAX * DEG_MAX];  // ELL: src index per slot
__device__ __align__(16) float g_ex[N_MAX * DEG_MAX];    // ELL: exp(alpha) per slot
__device__ int   g_is64;                                 // edge_index dtype flag

// ---------------------------------------------------------------------------
// dtype detection
// ---------------------------------------------------------------------------
__global__ void k_detect(const void* ei, int E, int N) {
    __shared__ int bad;
    if (threadIdx.x == 0) bad = 0;
    __syncthreads();
    int samples = min(2 * E, 4096) / 2;
    const long long* p = (const long long*)ei;
    for (int t = threadIdx.x; t < samples; t += blockDim.x) {
        long long v = p[t];
        if (v < 0 || v >= (long long)N) bad = 1;
    }
    __syncthreads();
    if (threadIdx.x == 0) g_is64 = bad ? 0 : 1;
}

__device__ __forceinline__ void load_edge(const void* ei, int e, int E, int N,
                                          int& s, int& d) {
    if (e < E) {
        if (g_is64) {
            s = (int)((const long long*)ei)[e];
            d = (int)((const long long*)ei)[E + e];
        } else {
            s = ((const int*)ei)[e];
            d = ((const int*)ei)[E + e];
        }
    } else {
        s = d = e - E;
    }
    s = min(max(s, 0), N - 1);
    d = min(max(d, 0), N - 1);
}

// ---------------------------------------------------------------------------
// wvec: w_s = W @ att_s, w_d = W @ att_d  (one warp per row)
// ---------------------------------------------------------------------------
__global__ void k_wvec(const float* __restrict__ W,
                       const float* __restrict__ att_s,
                       const float* __restrict__ att_d) {
    int gt   = blockIdx.x * blockDim.x + threadIdx.x;
    int row  = gt >> 5;
    int lane = gt & 31;
    if (row >= D) return;

    float4 wv = *(const float4*)&W[row * 128 + lane * 4];
    float4 s4 = *(const float4*)&att_s[lane * 4];
    float4 d4 = *(const float4*)&att_d[lane * 4];
    float s = wv.x * s4.x + wv.y * s4.y + wv.z * s4.z + wv.w * s4.w;
    float d = wv.x * d4.x + wv.y * d4.y + wv.z * d4.z + wv.w * d4.w;
#pragma unroll
    for (int o = 16; o > 0; o >>= 1) {
        s += __shfl_xor_sync(0xffffffffu, s, o);
        d += __shfl_xor_sync(0xffffffffu, d, o);
    }
    if (lane == 0) {
        g_ws[row] = s;
        g_wd[row] = d;
    }
}

// ---------------------------------------------------------------------------
// scores: a_src[n] = x[n]·w_s, a_dst[n] = x[n]·w_d
// ---------------------------------------------------------------------------
__global__ void k_scores(const float* __restrict__ x, int N) {
    int gt   = blockIdx.x * blockDim.x + threadIdx.x;
    int node = gt >> 5;
    int lane = gt & 31;
    if (node >= N) return;

    float4 xv = *(const float4*)&x[node * 128 + lane * 4];
    float4 s4 = *(const float4*)&g_ws[lane * 4];
    float4 d4 = *(const float4*)&g_wd[lane * 4];

    float s = xv.x * s4.x + xv.y * s4.y + xv.z * s4.z + xv.w * s4.w;
    float d = xv.x * d4.x + xv.y * d4.y + xv.z * d4.z + xv.w * d4.w;
#pragma unroll
    for (int o = 16; o > 0; o >>= 1) {
        s += __shfl_xor_sync(0xffffffffu, s, o);
        d += __shfl_xor_sync(0xffffffffu, d, o);
    }
    if (lane == 0) {
        g_asrc[node] = s;
        g_adst[node] = d;
    }
}

// ---------------------------------------------------------------------------
// ELL fill (score-independent): bucket src indices by dst. No gathers.
// ---------------------------------------------------------------------------
__global__ void k_fill(const void* __restrict__ ei, int E, int ET, int N) {
    int e = blockIdx.x * blockDim.x + threadIdx.x;
    if (e >= ET) return;
    int s, d;
    load_edge(ei, e, E, N, s, d);
    int pos = atomicAdd(&g_cursor[d], 1);
    if (pos < DEG_MAX)
        g_esrc[d * DEG_MAX + pos] = s;
}

// ---------------------------------------------------------------------------
// exp pass: warp per node. Coalesced seg read/write; only a_src gather is
// random (200 KB table, largely L1-resident). MUFU exp runs here with slack.
// ---------------------------------------------------------------------------
__global__ void k_exp(int N) {
    int gt   = blockIdx.x * blockDim.x + threadIdx.x;
    int node = gt >> 5;
    int lane = gt & 31;
    if (node >= N) return;

    const int deg = min(g_cursor[node], DEG_MAX);
    const float adst = g_adst[node];
    const int base = node * DEG_MAX;

    for (int j = lane; j < deg; j += 32) {
        int s = g_esrc[base + j];
        float al = g_asrc[s] + adst;
        al = (al > 0.f) ? al : NEG_SLOPE * al;
        g_ex[base + j] = __expf(al);
    }
}

// ---------------------------------------------------------------------------
// GEMM: h = x @ W via tf32 wmma; epilogue writes fp16 mirror.
// ---------------------------------------------------------------------------
__global__ __launch_bounds__(256) void k_gemm_tc(const float* __restrict__ x,
                                                 const float* __restrict__ W,
                                                 int N) {
    __shared__ __align__(16) float sA[128 * LDA];
    __shared__ __align__(16) float sB[TK * LDB];

    const int tid = threadIdx.x;
    const int wid = tid >> 5;
    const int lane = tid & 31;
    const int warp_m = wid & 3;
    const int warp_n = wid >> 2;
    const int rowBase = blockIdx.x * 128;

    wmma::fragment<wmma::accumulator, 16, 16, 8, float> c[2][4];
#pragma unroll
    for (int i = 0; i < 2; i++)
#pragma unroll
        for (int j = 0; j < 4; j++) wmma::fill_fragment(c[i][j], 0.0f);

    for (int k0 = 0; k0 < 128; k0 += TK) {
#pragma unroll
        for (int t = tid; t < 128 * (TK / 4); t += 256) {
            int r  = t / (TK / 4);
            int cq = t % (TK / 4);
            float4 v = make_float4(0.f, 0.f, 0.f, 0.f);
            int row = rowBase + r;
            if (row < N) v = *(const float4*)&x[row * 128 + k0 + cq * 4];
            *(float4*)&sA[r * LDA + cq * 4] = v;
        }
#pragma unroll
        for (int t = tid; t < TK * (128 / 4); t += 256) {
            int r  = t / 32;
            int cq = t % 32;
            *(float4*)&sB[r * LDB + cq * 4] =
                *(const float4*)&W[(k0 + r) * 128 + cq * 4];
        }
        __syncthreads();

#pragma unroll
        for (int kk = 0; kk < TK; kk += 8) {
            wmma::fragment<wmma::matrix_a, 16, 16, 8, wmma::precision::tf32,
                           wmma::row_major> a[2];
            wmma::fragment<wmma::matrix_b, 16, 16, 8, wmma::precision::tf32,
                           wmma::row_major> b[4];
#pragma unroll
            for (int i = 0; i < 2; i++) {
                wmma::load_matrix_sync(a[i],
                    &sA[(warp_m * 32 + i * 16) * LDA + kk], LDA);
#pragma unroll
                for (int t = 0; t < a[i].num_elements; t++)
                    a[i].x[t] = wmma::__float_to_tf32(a[i].x[t]);
            }
#pragma unroll
            for (int j = 0; j < 4; j++) {
                wmma::load_matrix_sync(b[j],
                    &sB[kk * LDB + warp_n * 64 + j * 16], LDB);
#pragma unroll
                for (int t = 0; t < b[j].num_elements; t++)
                    b[j].x[t] = wmma::__float_to_tf32(b[j].x[t]);
            }
#pragma unroll
            for (int i = 0; i < 2; i++)
#pragma unroll
                for (int j = 0; j < 4; j++)
                    wmma::mma_sync(c[i][j], a[i], b[j], c[i][j]);
        }
        __syncthreads();
    }

#pragma unroll
    for (int i = 0; i < 2; i++) {
        int row = rowBase + warp_m * 32 + i * 16;
#pragma unroll
        for (int j = 0; j < 4; j++) {
            wmma::store_matrix_sync(&g_h[row * 128 + warp_n * 64 + j * 16],
                                    c[i][j], 128, wmma::mem_row_major);
        }
    }
    __syncthreads();

    // epilogue: fp16 mirror
#pragma unroll
    for (int r = 0; r < 16; r++) {
        int row = rowBase + wid * 16 + r;
        float4 hv = *(const float4*)&g_h[row * 128 + lane * 4];
        __half2 hp0 = __floats2half2_rn(hv.x, hv.y);
        __half2 hp1 = __floats2half2_rn(hv.z, hv.w);
        uint2 packed = make_uint2(*(unsigned*)&hp0, *(unsigned*)&hp1);
        *(uint2*)&g_hh[row * 128 + lane * 4] = packed;
    }
}

// ---------------------------------------------------------------------------
// SINGLE-PASS aggregation: warp per node; fp16 gather, fp32 accumulate;
// exp precomputed by k_exp (two coalesced seg streams).
// ---------------------------------------------------------------------------
__global__ __launch_bounds__(256, 6) void k_agg(float* __restrict__ out, int N) {
    int gt   = blockIdx.x * blockDim.x + threadIdx.x;
    int node = gt >> 5;
    int lane = gt & 31;
    if (node >= N) return;

    const int deg = min(g_cursor[node], DEG_MAX);
    const int base = node * DEG_MAX;

    float ssum = 0.f;
    float ax = 0.f, ay = 0.f, az = 0.f, aw = 0.f;

    for (int j0 = 0; j0 < deg; j0 += 32) {
        int j = j0 + lane;
        int s = 0;
        float e = 0.f;
        if (j < deg) {
            s = g_esrc[base + j];
            e = g_ex[base + j];
        }
        ssum += e;
        const int cnt = min(32, deg - j0);
        int t = 0;
        for (; t + 4 <= cnt; t += 4) {
            int   s0 = __shfl_sync(0xffffffffu, s, t);
            int   s1 = __shfl_sync(0xffffffffu, s, t + 1);
            int   s2 = __shfl_sync(0xffffffffu, s, t + 2);
            int   s3 = __shfl_sync(0xffffffffu, s, t + 3);
            float e0 = __shfl_sync(0xffffffffu, e, t);
            float e1 = __shfl_sync(0xffffffffu, e, t + 1);
            float e2 = __shfl_sync(0xffffffffu, e, t + 2);
            float e3 = __shfl_sync(0xffffffffu, e, t + 3);
            uint2 r0 = *(const uint2*)&g_hh[s0 * 128 + lane * 4];
            uint2 r1 = *(const uint2*)&g_hh[s1 * 128 + lane * 4];
            uint2 r2 = *(const uint2*)&g_hh[s2 * 128 + lane * 4];
            uint2 r3 = *(const uint2*)&g_hh[s3 * 128 + lane * 4];
            float2 a0 = __half22float2(*(__half2*)&r0.x);
            float2 b0 = __half22float2(*(__half2*)&r0.y);
            float2 a1 = __half22float2(*(__half2*)&r1.x);
            float2 b1 = __half22float2(*(__half2*)&r1.y);
            float2 a2 = __half22float2(*(__half2*)&r2.x);
            float2 b2 = __half22float2(*(__half2*)&r2.y);
            float2 a3 = __half22float2(*(__half2*)&r3.x);
            float2 b3 = __half22float2(*(__half2*)&r3.y);
            ax = fmaf(a0.x, e0, ax); ay = fmaf(a0.y, e0, ay);
            az = fmaf(b0.x, e0, az); aw = fmaf(b0.y, e0, aw);
            ax = fmaf(a1.x, e1, ax); ay = fmaf(a1.y, e1, ay);
            az = fmaf(b1.x, e1, az); aw = fmaf(b1.y, e1, aw);
            ax = fmaf(a2.x, e2, ax); ay = fmaf(a2.y, e2, ay);
            az = fmaf(b2.x, e2, az); aw = fmaf(b2.y, e2, aw);
            ax = fmaf(a3.x, e3, ax); ay = fmaf(a3.y, e3, ay);
            az = fmaf(b3.x, e3, az); aw = fmaf(b3.y, e3, aw);
        }
        for (; t < cnt; t++) {
            int   ss = __shfl_sync(0xffffffffu, s, t);
            float ee = __shfl_sync(0xffffffffu, e, t);
            uint2 rr = *(const uint2*)&g_hh[ss * 128 + lane * 4];
            float2 f01 = __half22float2(*(__half2*)&rr.x);
            float2 f23 = __half22float2(*(__half2*)&rr.y);
            ax = fmaf(f01.x, ee, ax);
            ay = fmaf(f01.y, ee, ay);
            az = fmaf(f23.x, ee, az);
            aw = fmaf(f23.y, ee, aw);
        }
    }

#pragma unroll
    for (int o = 16; o > 0; o >>= 1)
        ssum += __shfl_xor_sync(0xffffffffu, ssum, o);
    const float inv = 1.0f / (ssum + EPS_DEN);

    *(float4*)&out[node * 128 + lane * 4] =
        make_float4(ax * inv, ay * inv, az * inv, aw * inv);

    if (lane == 0) g_cursor[node] = 0;   // clean for next graph replay
}

// ---------------------------------------------------------------------------
// 3-stream schedule:
//   s1: detect -> fill ------\
//   s2: wvec -> scores -------+-> exp(s1) --\
//   s0: gemm_tc --------------------------- +-> agg(s0)
// ---------------------------------------------------------------------------
extern "C" void kernel_launch(void* const* d_in, const int* in_sizes, int n_in,
                              void* d_out, int out_size) {
    const float* x     = (const float*)d_in[0];
    const void*  ei    = d_in[1];
    const float* W     = (const float*)d_in[2];
    const float* att_s = (const float*)d_in[3];
    const float* att_d = (const float*)d_in[4];
    float*       out   = (float*)d_out;

    const int N  = in_sizes[0] / D;
    const int E  = in_sizes[1] / 2;
    const int ET = E + N;

    static cudaStream_t s1 = nullptr, s2 = nullptr;
    static cudaEvent_t evFork = nullptr, evScores = nullptr, evSide = nullptr;
    if (s1 == nullptr) {
        cudaStreamCreateWithFlags(&s1, cudaStreamNonBlocking);
        cudaStreamCreateWithFlags(&s2, cudaStreamNonBlocking);
        cudaEventCreateWithFlags(&evFork,   cudaEventDisableTiming);
        cudaEventCreateWithFlags(&evScores, cudaEventDisableTiming);
        cudaEventCreateWithFlags(&evSide,   cudaEventDisableTiming);
    }

    cudaEventRecord(evFork, 0);
    cudaStreamWaitEvent(s1, evFork, 0);
    cudaStreamWaitEvent(s2, evFork, 0);

    // s1: edge bucketing (score-independent)
    k_detect<<<1, 256, 0, s1>>>(ei, E, N);
    // s2: score chain
    k_wvec  <<<(D * 32 + 255) / 256, 256, 0, s2>>>(W, att_s, att_d);
    k_scores<<<(N * 32 + 255) / 256, 256, 0, s2>>>(x, N);
    // s1 (4th submitted -> profiler window): slimmed fill
    k_fill  <<<(ET + 255) / 256, 256, 0, s1>>>(ei, E, ET, N);

    // exp pass on s1 after scores (s2) complete
    cudaEventRecord(evScores, s2);
    cudaStreamWaitEvent(s1, evScores, 0);
    k_exp<<<(N * 32 + 255) / 256, 256, 0, s1>>>(N);

    // s0: projection (concurrent with all of the above)
    k_gemm_tc<<<(N + 127) / 128, 256>>>(x, W, N);

    // join side chain into s0, then aggregate
    cudaEventRecord(evSide, s1);
    cudaStreamWaitEvent(0, evSide, 0);
    {
        long long threads = (long long)N * 32;
        int blocks = (int)((threads + 255) / 256);
        k_agg<<<blocks, 256>>>(out, N);
    }
}

// round 16
// speedup vs baseline: 1.0529x; 1.0529x over previous
#include <cuda_runtime.h>
#include <cuda_fp16.h>
#include <math_constants.h>
#include <mma.h>

using namespace nvcuda;

#define D 128
#define NEG_SLOPE 0.2f
#define EPS_DEN 1e-16f

#define N_MAX 50048
#define DEG_MAX 192      // >> max expected degree (~60 for this dist)

#define TK 32
#define LDA (TK + 4)
#define LDB (D + 4)

// ---- static scratch (no device allocations allowed) ----
__device__ __align__(16) __half g_hh[N_MAX * D];         // fp16 projected features
__device__ __align__(16) float g_ws[D];                  // W @ att_src
__device__ __align__(16) float g_wd[D];                  // W @ att_dst
__device__ float g_asrc[N_MAX];
__device__ float g_adst[N_MAX];
__device__ int   g_cursor[N_MAX];                        // per-dst cursor == degree
__device__ __align__(16) int2 g_ell[N_MAX * DEG_MAX];    // {src, float_bits(exp(alpha))}
__device__ int   g_is64;                                 // edge_index dtype flag

// ---------------------------------------------------------------------------
// dtype detection
// ---------------------------------------------------------------------------
__global__ void k_detect(const void* ei, int E, int N) {
    __shared__ int bad;
    if (threadIdx.x == 0) bad = 0;
    __syncthreads();
    int samples = min(2 * E, 4096) / 2;
    const long long* p = (const long long*)ei;
    for (int t = threadIdx.x; t < samples; t += blockDim.x) {
        long long v = p[t];
        if (v < 0 || v >= (long long)N) bad = 1;
    }
    __syncthreads();
    if (threadIdx.x == 0) g_is64 = bad ? 0 : 1;
}

__device__ __forceinline__ void load_edge(const void* ei, int e, int E, int N,
                                          int& s, int& d) {
    if (e < E) {
        if (g_is64) {
            s = (int)((const long long*)ei)[e];
            d = (int)((const long long*)ei)[E + e];
        } else {
            s = ((const int*)ei)[e];
            d = ((const int*)ei)[E + e];
        }
    } else {
        s = d = e - E;
    }
    s = min(max(s, 0), N - 1);
    d = min(max(d, 0), N - 1);
}

// ---------------------------------------------------------------------------
// wvec: w_s = W @ att_s, w_d = W @ att_d  (one warp per row)
// ---------------------------------------------------------------------------
__global__ void k_wvec(const float* __restrict__ W,
                       const float* __restrict__ att_s,
                       const float* __restrict__ att_d) {
    int gt   = blockIdx.x * blockDim.x + threadIdx.x;
    int row  = gt >> 5;
    int lane = gt & 31;
    if (row >= D) return;

    float4 wv = *(const float4*)&W[row * 128 + lane * 4];
    float4 s4 = *(const float4*)&att_s[lane * 4];
    float4 d4 = *(const float4*)&att_d[lane * 4];
    float s = wv.x * s4.x + wv.y * s4.y + wv.z * s4.z + wv.w * s4.w;
    float d = wv.x * d4.x + wv.y * d4.y + wv.z * d4.z + wv.w * d4.w;
#pragma unroll
    for (int o = 16; o > 0; o >>= 1) {
        s += __shfl_xor_sync(0xffffffffu, s, o);
        d += __shfl_xor_sync(0xffffffffu, d, o);
    }
    if (lane == 0) {
        g_ws[row] = s;
        g_wd[row] = d;
    }
}

// ---------------------------------------------------------------------------
// scores: a_src[n] = x[n]·w_s, a_dst[n] = x[n]·w_d
// ---------------------------------------------------------------------------
__global__ void k_scores(const float* __restrict__ x, int N) {
    int gt   = blockIdx.x * blockDim.x + threadIdx.x;
    int node = gt >> 5;
    int lane = gt & 31;
    if (node >= N) return;

    float4 xv = *(const float4*)&x[node * 128 + lane * 4];
    float4 s4 = *(const float4*)&g_ws[lane * 4];
    float4 d4 = *(const float4*)&g_wd[lane * 4];

    float s = xv.x * s4.x + xv.y * s4.y + xv.z * s4.z + xv.w * s4.w;
    float d = xv.x * d4.x + xv.y * d4.y + xv.z * d4.z + xv.w * d4.w;
#pragma unroll
    for (int o = 16; o > 0; o >>= 1) {
        s += __shfl_xor_sync(0xffffffffu, s, o);
        d += __shfl_xor_sync(0xffffffffu, d, o);
    }
    if (lane == 0) {
        g_asrc[node] = s;
        g_adst[node] = d;
    }
}

// ---------------------------------------------------------------------------
// GEMM: h = x @ W via tf32 wmma. fp16-ONLY output: C fragments staged
// through smem (reusing sA) 32 rows at a time, converted, stored to g_hh.
// ---------------------------------------------------------------------------
__global__ __launch_bounds__(256) void k_gemm_tc(const float* __restrict__ x,
                                                 const float* __restrict__ W,
                                                 int N) {
    __shared__ __align__(16) float sA[128 * LDA];   // also reused as C staging
    __shared__ __align__(16) float sB[TK * LDB];

    const int tid = threadIdx.x;
    const int wid = tid >> 5;
    const int warp_m = wid & 3;
    const int warp_n = wid >> 2;
    const int rowBase = blockIdx.x * 128;

    wmma::fragment<wmma::accumulator, 16, 16, 8, float> c[2][4];
#pragma unroll
    for (int i = 0; i < 2; i++)
#pragma unroll
        for (int j = 0; j < 4; j++) wmma::fill_fragment(c[i][j], 0.0f);

    for (int k0 = 0; k0 < 128; k0 += TK) {
#pragma unroll
        for (int t = tid; t < 128 * (TK / 4); t += 256) {
            int r  = t / (TK / 4);
            int cq = t % (TK / 4);
            float4 v = make_float4(0.f, 0.f, 0.f, 0.f);
            int row = rowBase + r;
            if (row < N) v = *(const float4*)&x[row * 128 + k0 + cq * 4];
            *(float4*)&sA[r * LDA + cq * 4] = v;
        }
#pragma unroll
        for (int t = tid; t < TK * (128 / 4); t += 256) {
            int r  = t / 32;
            int cq = t % 32;
            *(float4*)&sB[r * LDB + cq * 4] =
                *(const float4*)&W[(k0 + r) * 128 + cq * 4];
        }
        __syncthreads();

#pragma unroll
        for (int kk = 0; kk < TK; kk += 8) {
            wmma::fragment<wmma::matrix_a, 16, 16, 8, wmma::precision::tf32,
                           wmma::row_major> a[2];
            wmma::fragment<wmma::matrix_b, 16, 16, 8, wmma::precision::tf32,
                           wmma::row_major> b[4];
#pragma unroll
            for (int i = 0; i < 2; i++) {
                wmma::load_matrix_sync(a[i],
                    &sA[(warp_m * 32 + i * 16) * LDA + kk], LDA);
#pragma unroll
                for (int t = 0; t < a[i].num_elements; t++)
                    a[i].x[t] = wmma::__float_to_tf32(a[i].x[t]);
            }
#pragma unroll
            for (int j = 0; j < 4; j++) {
                wmma::load_matrix_sync(b[j],
                    &sB[kk * LDB + warp_n * 64 + j * 16], LDB);
#pragma unroll
                for (int t = 0; t < b[j].num_elements; t++)
                    b[j].x[t] = wmma::__float_to_tf32(b[j].x[t]);
            }
#pragma unroll
            for (int i = 0; i < 2; i++)
#pragma unroll
                for (int j = 0; j < 4; j++)
                    wmma::mma_sync(c[i][j], a[i], b[j], c[i][j]);
        }
        __syncthreads();
    }

    // C epilogue: 4 rounds; round r stages rows [r*32, r*32+32) in sC (=sA),
    // then all threads convert to fp16 and store to g_hh.
    float* sC = sA;   // 32 rows x 128 cols fp32 = 16 KB <= sizeof(sA)
    const int lr = tid >> 3;            // 0..31 (row within round)
    const int lc = (tid & 7) * 16;      // 0,16,...,112 (col chunk)
#pragma unroll
    for (int r = 0; r < 4; r++) {
        if (warp_m == r) {
#pragma unroll
            for (int i = 0; i < 2; i++)
#pragma unroll
                for (int j = 0; j < 4; j++)
                    wmma::store_matrix_sync(
                        &sC[(i * 16) * 128 + warp_n * 64 + j * 16],
                        c[i][j], 128, wmma::mem_row_major);
        }
        __syncthreads();
        {
            int grow = rowBase + r * 32 + lr;   // < N_MAX always (391*128)
            const float4* src = (const float4*)&sC[lr * 128 + lc];
            uint4 outv[2];
#pragma unroll
            for (int q = 0; q < 2; q++) {
                float4 f0 = src[q * 2 + 0];
                float4 f1 = src[q * 2 + 1];
                __half2 h0 = __floats2half2_rn(f0.x, f0.y);
                __half2 h1 = __floats2half2_rn(f0.z, f0.w);
                __half2 h2 = __floats2half2_rn(f1.x, f1.y);
                __half2 h3 = __floats2half2_rn(f1.z, f1.w);
                outv[q] = make_uint4(*(unsigned*)&h0, *(unsigned*)&h1,
                                     *(unsigned*)&h2, *(unsigned*)&h3);
            }
            *(uint4*)&g_hh[grow * 128 + lc + 0] = outv[0];
            *(uint4*)&g_hh[grow * 128 + lc + 8] = outv[1];
        }
        __syncthreads();
    }
}

// ---------------------------------------------------------------------------
// ELL fill (fused): bucket edges by dst; store {src, exp(leaky(a_s+a_d))}.
// ---------------------------------------------------------------------------
__global__ void k_fill(const void* __restrict__ ei, int E, int ET, int N) {
    int e = blockIdx.x * blockDim.x + threadIdx.x;
    if (e >= ET) return;
    int s, d;
    load_edge(ei, e, E, N, s, d);
    float al = g_asrc[s] + g_adst[d];
    al = (al > 0.f) ? al : NEG_SLOPE * al;
    float ex = __expf(al);
    int pos = atomicAdd(&g_cursor[d], 1);
    if (pos < DEG_MAX)
        g_ell[d * DEG_MAX + pos] = make_int2(s, __float_as_int(ex));
}

// ---------------------------------------------------------------------------
// SINGLE-PASS aggregation, broadcast-load style: warp per node.
// (src, ex) read via warp-uniform int4 loads (2 edges per LDG.128, L1-hot
// broadcast) — no shuffles; every lane accumulates the full ssum, so no
// final reduction either. fp16 feature gather, fp32 accumulate.
// ---------------------------------------------------------------------------
__global__ __launch_bounds__(256, 6) void k_agg(float* __restrict__ out, int N) {
    int gt   = blockIdx.x * blockDim.x + threadIdx.x;
    int node = gt >> 5;
    int lane = gt & 31;
    if (node >= N) return;

    const int deg = min(g_cursor[node], DEG_MAX);
    const int2* seg = &g_ell[node * DEG_MAX];
    const int lo = lane * 4;

    float ssum = 0.f;
    float ax = 0.f, ay = 0.f, az = 0.f, aw = 0.f;

    int t = 0;
    for (; t + 4 <= deg; t += 4) {
        int4 q0 = *(const int4*)&seg[t];       // edges t, t+1
        int4 q1 = *(const int4*)&seg[t + 2];   // edges t+2, t+3
        float e0 = __int_as_float(q0.y);
        float e1 = __int_as_float(q0.w);
        float e2 = __int_as_float(q1.y);
        float e3 = __int_as_float(q1.w);
        uint2 r0 = *(const uint2*)&g_hh[q0.x * 128 + lo];
        uint2 r1 = *(const uint2*)&g_hh[q0.z * 128 + lo];
        uint2 r2 = *(const uint2*)&g_hh[q1.x * 128 + lo];
        uint2 r3 = *(const uint2*)&g_hh[q1.z * 128 + lo];
        ssum += (e0 + e1) + (e2 + e3);
        float2 a0 = __half22float2(*(__half2*)&r0.x);
        float2 b0 = __half22float2(*(__half2*)&r0.y);
        float2 a1 = __half22float2(*(__half2*)&r1.x);
        float2 b1 = __half22float2(*(__half2*)&r1.y);
        float2 a2 = __half22float2(*(__half2*)&r2.x);
        float2 b2 = __half22float2(*(__half2*)&r2.y);
        float2 a3 = __half22float2(*(__half2*)&r3.x);
        float2 b3 = __half22float2(*(__half2*)&r3.y);
        ax = fmaf(a0.x, e0, ax); ay = fmaf(a0.y, e0, ay);
        az = fmaf(b0.x, e0, az); aw = fmaf(b0.y, e0, aw);
        ax = fmaf(a1.x, e1, ax); ay = fmaf(a1.y, e1, ay);
        az = fmaf(b1.x, e1, az); aw = fmaf(b1.y, e1, aw);
        ax = fmaf(a2.x, e2, ax); ay = fmaf(a2.y, e2, ay);
        az = fmaf(b2.x, e2, az); aw = fmaf(b2.y, e2, aw);
        ax = fmaf(a3.x, e3, ax); ay = fmaf(a3.y, e3, ay);
        az = fmaf(b3.x, e3, az); aw = fmaf(b3.y, e3, aw);
    }
    for (; t < deg; t++) {
        int2 p = seg[t];
        float e = __int_as_float(p.y);
        ssum += e;
        uint2 rr = *(const uint2*)&g_hh[p.x * 128 + lo];
        float2 f01 = __half22float2(*(__half2*)&rr.x);
        float2 f23 = __half22float2(*(__half2*)&rr.y);
        ax = fmaf(f01.x, e, ax);
        ay = fmaf(f01.y, e, ay);
        az = fmaf(f23.x, e, az);
        aw = fmaf(f23.y, e, aw);
    }

    const float inv = 1.0f / (ssum + EPS_DEN);
    *(float4*)&out[node * 128 + lo] =
        make_float4(ax * inv, ay * inv, az * inv, aw * inv);

    if (lane == 0) g_cursor[node] = 0;   // clean for next graph replay
}

// ---------------------------------------------------------------------------
// Schedule:
//   s1: wvec -> scores -> fill(waits detect) --\
//   s2: detect --------------------------------+
//   s0: gemm_tc ------------------------------- +-> agg
// Submission order puts gemm_tc 4th (profiler window).
// ---------------------------------------------------------------------------
extern "C" void kernel_launch(void* const* d_in, const int* in_sizes, int n_in,
                              void* d_out, int out_size) {
    const float* x     = (const float*)d_in[0];
    const void*  ei    = d_in[1];
    const float* W     = (const float*)d_in[2];
    const float* att_s = (const float*)d_in[3];
    const float* att_d = (const float*)d_in[4];
    float*       out   = (float*)d_out;

    const int N  = in_sizes[0] / D;
    const int E  = in_sizes[1] / 2;
    const int ET = E + N;

    static cudaStream_t s1 = nullptr, s2 = nullptr;
    static cudaEvent_t evFork = nullptr, evDetect = nullptr, evSide = nullptr;
    if (s1 == nullptr) {
        cudaStreamCreateWithFlags(&s1, cudaStreamNonBlocking);
        cudaStreamCreateWithFlags(&s2, cudaStreamNonBlocking);
        cudaEventCreateWithFlags(&evFork,   cudaEventDisableTiming);
        cudaEventCreateWithFlags(&evDetect, cudaEventDisableTiming);
        cudaEventCreateWithFlags(&evSide,   cudaEventDisableTiming);
    }

    cudaEventRecord(evFork, 0);
    cudaStreamWaitEvent(s1, evFork, 0);
    cudaStreamWaitEvent(s2, evFork, 0);

    // 1) side: w vectors
    k_wvec  <<<(D * 32 + 255) / 256, 256, 0, s1>>>(W, att_s, att_d);
    // 2) dtype detection (parallel, tiny)
    k_detect<<<1, 256, 0, s2>>>(ei, E, N);
    // 3) side: per-node scores
    k_scores<<<(N * 32 + 255) / 256, 256, 0, s1>>>(x, N);
    // 4) main: projection (profiler window lands here)
    k_gemm_tc<<<(N + 127) / 128, 256>>>(x, W, N);
    // 5) side: fill (needs scores [s1-serial] + detect [event])
    cudaEventRecord(evDetect, s2);
    cudaStreamWaitEvent(s1, evDetect, 0);
    k_fill<<<(ET + 255) / 256, 256, 0, s1>>>(ei, E, ET, N);
    // 6) join side into main, aggregate
    cudaEventRecord(evSide, s1);
    cudaStreamWaitEvent(0, evSide, 0);
    {
        long long threads = (long long)N * 32;
        int blocks = (int)((threads + 255) / 256);
        k_agg<<<blocks, 256>>>(out, N);
    }
}

// round 17
// speedup vs baseline: 1.2501x; 1.1873x over previous
#include <cuda_runtime.h>
#include <cuda_fp16.h>
#include <math_constants.h>
#include <mma.h>

using namespace nvcuda;

#define D 128
#define NEG_SLOPE 0.2f
#define EPS_DEN 1e-16f

#define N_MAX 50048
#define DEG_MAX 192      // >> max expected degree (~60 for this dist)

// fp16 GEMM tile config: block 128x64, warp 32x32, 8 warps (4m x 2n)
#define LDX 136          // sX leading dim in halfs (128 + 8 pad)
#define LDW 72           // sW leading dim in halfs (64 + 8 pad)

// ---- static scratch (no device allocations allowed) ----
__device__ __align__(16) __half g_hh[N_MAX * D];         // fp16 projected features
__device__ __align__(16) float g_ws[D];                  // W @ att_src
__device__ __align__(16) float g_wd[D];                  // W @ att_dst
__device__ float g_asrc[N_MAX];
__device__ float g_adst[N_MAX];
__device__ int   g_cursor[N_MAX];                        // per-dst cursor == degree
__device__ __align__(16) int2 g_ell[N_MAX * DEG_MAX];    // {src, float_bits(exp(alpha))}
__device__ int   g_is64;                                 // edge_index dtype flag

// ---------------------------------------------------------------------------
// dtype detection
// ---------------------------------------------------------------------------
__global__ void k_detect(const void* ei, int E, int N) {
    __shared__ int bad;
    if (threadIdx.x == 0) bad = 0;
    __syncthreads();
    int samples = min(2 * E, 4096) / 2;
    const long long* p = (const long long*)ei;
    for (int t = threadIdx.x; t < samples; t += blockDim.x) {
        long long v = p[t];
        if (v < 0 || v >= (long long)N) bad = 1;
    }
    __syncthreads();
    if (threadIdx.x == 0) g_is64 = bad ? 0 : 1;
}

__device__ __forceinline__ void load_edge(const void* ei, int e, int E, int N,
                                          int& s, int& d) {
    if (e < E) {
        if (g_is64) {
            s = (int)((const long long*)ei)[e];
            d = (int)((const long long*)ei)[E + e];
        } else {
            s = ((const int*)ei)[e];
            d = ((const int*)ei)[E + e];
        }
    } else {
        s = d = e - E;
    }
    s = min(max(s, 0), N - 1);
    d = min(max(d, 0), N - 1);
}

// ---------------------------------------------------------------------------
// wvec: w_s = W @ att_s, w_d = W @ att_d  (one warp per row)
// ---------------------------------------------------------------------------
__global__ void k_wvec(const float* __restrict__ W,
                       const float* __restrict__ att_s,
                       const float* __restrict__ att_d) {
    int gt   = blockIdx.x * blockDim.x + threadIdx.x;
    int row  = gt >> 5;
    int lane = gt & 31;
    if (row >= D) return;

    float4 wv = *(const float4*)&W[row * 128 + lane * 4];
    float4 s4 = *(const float4*)&att_s[lane * 4];
    float4 d4 = *(const float4*)&att_d[lane * 4];
    float s = wv.x * s4.x + wv.y * s4.y + wv.z * s4.z + wv.w * s4.w;
    float d = wv.x * d4.x + wv.y * d4.y + wv.z * d4.z + wv.w * d4.w;
#pragma unroll
    for (int o = 16; o > 0; o >>= 1) {
        s += __shfl_xor_sync(0xffffffffu, s, o);
        d += __shfl_xor_sync(0xffffffffu, d, o);
    }
    if (lane == 0) {
        g_ws[row] = s;
        g_wd[row] = d;
    }
}

// ---------------------------------------------------------------------------
// scores: a_src[n] = x[n]·w_s, a_dst[n] = x[n]·w_d
// ---------------------------------------------------------------------------
__global__ void k_scores(const float* __restrict__ x, int N) {
    int gt   = blockIdx.x * blockDim.x + threadIdx.x;
    int node = gt >> 5;
    int lane = gt & 31;
    if (node >= N) return;

    float4 xv = *(const float4*)&x[node * 128 + lane * 4];
    float4 s4 = *(const float4*)&g_ws[lane * 4];
    float4 d4 = *(const float4*)&g_wd[lane * 4];

    float s = xv.x * s4.x + xv.y * s4.y + xv.z * s4.z + xv.w * s4.w;
    float d = xv.x * d4.x + xv.y * d4.y + xv.z * d4.z + xv.w * d4.w;
#pragma unroll
    for (int o = 16; o > 0; o >>= 1) {
        s += __shfl_xor_sync(0xffffffffu, s, o);
        d += __shfl_xor_sync(0xffffffffu, d, o);
    }
    if (lane == 0) {
        g_asrc[node] = s;
        g_adst[node] = d;
    }
}

// ---------------------------------------------------------------------------
// GEMM: h = x @ W via fp16 wmma m16n16k16, fp32 accumulate, fp16 output.
// Block 128x64 (grid 391 x 2), 8 warps of 32x32; full K=128 staged in fp16.
// ---------------------------------------------------------------------------
__global__ __launch_bounds__(256) void k_gemm_tc(const float* __restrict__ x,
                                                 const float* __restrict__ W,
                                                 int N) {
    __shared__ __align__(16) __half sX[128 * LDX];   // 128 rows x K=128
    __shared__ __align__(16) __half sW[128 * LDW];   // K=128 rows x 64 cols
    __shared__ __align__(16) float  sC[128 * 64];    // C staging (32 KB)

    const int tid = threadIdx.x;
    const int wid = tid >> 5;
    const int warp_m = wid & 3;        // 0..3 -> 32-row slice
    const int warp_n = wid >> 2;       // 0..1 -> 32-col slice
    const int rowBase = blockIdx.x * 128;
    const int colBase = blockIdx.y * 64;

    // stage x tile (fp32 -> fp16): 128x128, 64 floats per thread
#pragma unroll
    for (int t = tid; t < 128 * 32; t += 256) {     // 32 float4 chunks per row
        int r  = t >> 5;
        int cq = t & 31;
        float4 v = make_float4(0.f, 0.f, 0.f, 0.f);
        int row = rowBase + r;
        if (row < N) v = *(const float4*)&x[row * 128 + cq * 4];
        __half2 h0 = __floats2half2_rn(v.x, v.y);
        __half2 h1 = __floats2half2_rn(v.z, v.w);
        *(uint2*)&sX[r * LDX + cq * 4] = make_uint2(*(unsigned*)&h0, *(unsigned*)&h1);
    }
    // stage W tile (fp32 -> fp16): 128 x 64
#pragma unroll
    for (int t = tid; t < 128 * 16; t += 256) {     // 16 float4 chunks per row
        int r  = t >> 4;
        int cq = t & 15;
        float4 v = *(const float4*)&W[r * 128 + colBase + cq * 4];
        __half2 h0 = __floats2half2_rn(v.x, v.y);
        __half2 h1 = __floats2half2_rn(v.z, v.w);
        *(uint2*)&sW[r * LDW + cq * 4] = make_uint2(*(unsigned*)&h0, *(unsigned*)&h1);
    }
    __syncthreads();

    wmma::fragment<wmma::accumulator, 16, 16, 16, float> c[2][2];
#pragma unroll
    for (int i = 0; i < 2; i++)
#pragma unroll
        for (int j = 0; j < 2; j++) wmma::fill_fragment(c[i][j], 0.0f);

#pragma unroll
    for (int kk = 0; kk < 128; kk += 16) {
        wmma::fragment<wmma::matrix_a, 16, 16, 16, __half, wmma::row_major> a[2];
        wmma::fragment<wmma::matrix_b, 16, 16, 16, __half, wmma::row_major> b[2];
#pragma unroll
        for (int i = 0; i < 2; i++)
            wmma::load_matrix_sync(a[i], &sX[(warp_m * 32 + i * 16) * LDX + kk], LDX);
#pragma unroll
        for (int j = 0; j < 2; j++)
            wmma::load_matrix_sync(b[j], &sW[kk * LDW + warp_n * 32 + j * 16], LDW);
#pragma unroll
        for (int i = 0; i < 2; i++)
#pragma unroll
            for (int j = 0; j < 2; j++)
                wmma::mma_sync(c[i][j], a[i], b[j], c[i][j]);
    }

    // stage C to smem, convert to fp16, store (rows < N_MAX always: 391*128)
#pragma unroll
    for (int i = 0; i < 2; i++)
#pragma unroll
        for (int j = 0; j < 2; j++)
            wmma::store_matrix_sync(
                &sC[(warp_m * 32 + i * 16) * 64 + warp_n * 32 + j * 16],
                c[i][j], 64, wmma::mem_row_major);
    __syncthreads();

#pragma unroll
    for (int t = tid; t < 128 * 8; t += 256) {      // 8 chunks of 8 floats per row
        int r  = t >> 3;
        int cq = t & 7;
        const float4* src = (const float4*)&sC[r * 64 + cq * 8];
        float4 f0 = src[0];
        float4 f1 = src[1];
        __half2 h0 = __floats2half2_rn(f0.x, f0.y);
        __half2 h1 = __floats2half2_rn(f0.z, f0.w);
        __half2 h2 = __floats2half2_rn(f1.x, f1.y);
        __half2 h3 = __floats2half2_rn(f1.z, f1.w);
        *(uint4*)&g_hh[(rowBase + r) * 128 + colBase + cq * 8] =
            make_uint4(*(unsigned*)&h0, *(unsigned*)&h1,
                       *(unsigned*)&h2, *(unsigned*)&h3);
    }
}

// ---------------------------------------------------------------------------
// ELL fill (fused): bucket edges by dst; store {src, exp(leaky(a_s+a_d))}.
// ---------------------------------------------------------------------------
__global__ void k_fill(const void* __restrict__ ei, int E, int ET, int N) {
    int e = blockIdx.x * blockDim.x + threadIdx.x;
    if (e >= ET) return;
    int s, d;
    load_edge(ei, e, E, N, s, d);
    float al = g_asrc[s] + g_adst[d];
    al = (al > 0.f) ? al : NEG_SLOPE * al;
    float ex = __expf(al);
    int pos = atomicAdd(&g_cursor[d], 1);
    if (pos < DEG_MAX)
        g_ell[d * DEG_MAX + pos] = make_int2(s, __float_as_int(ex));
}

// ---------------------------------------------------------------------------
// SINGLE-PASS aggregation, broadcast-load style: warp per node.
// ---------------------------------------------------------------------------
__global__ __launch_bounds__(256, 6) void k_agg(float* __restrict__ out, int N) {
    int gt   = blockIdx.x * blockDim.x + threadIdx.x;
    int node = gt >> 5;
    int lane = gt & 31;
    if (node >= N) return;

    const int deg = min(g_cursor[node], DEG_MAX);
    const int2* seg = &g_ell[node * DEG_MAX];
    const int lo = lane * 4;

    float ssum = 0.f;
    float ax = 0.f, ay = 0.f, az = 0.f, aw = 0.f;

    int t = 0;
    for (; t + 4 <= deg; t += 4) {
        int4 q0 = *(const int4*)&seg[t];
        int4 q1 = *(const int4*)&seg[t + 2];
        float e0 = __int_as_float(q0.y);
        float e1 = __int_as_float(q0.w);
        float e2 = __int_as_float(q1.y);
        float e3 = __int_as_float(q1.w);
        uint2 r0 = *(const uint2*)&g_hh[q0.x * 128 + lo];
        uint2 r1 = *(const uint2*)&g_hh[q0.z * 128 + lo];
        uint2 r2 = *(const uint2*)&g_hh[q1.x * 128 + lo];
        uint2 r3 = *(const uint2*)&g_hh[q1.z * 128 + lo];
        ssum += (e0 + e1) + (e2 + e3);
        float2 a0 = __half22float2(*(__half2*)&r0.x);
        float2 b0 = __half22float2(*(__half2*)&r0.y);
        float2 a1 = __half22float2(*(__half2*)&r1.x);
        float2 b1 = __half22float2(*(__half2*)&r1.y);
        float2 a2 = __half22float2(*(__half2*)&r2.x);
        float2 b2 = __half22float2(*(__half2*)&r2.y);
        float2 a3 = __half22float2(*(__half2*)&r3.x);
        float2 b3 = __half22float2(*(__half2*)&r3.y);
        ax = fmaf(a0.x, e0, ax); ay = fmaf(a0.y, e0, ay);
        az = fmaf(b0.x, e0, az); aw = fmaf(b0.y, e0, aw);
        ax = fmaf(a1.x, e1, ax); ay = fmaf(a1.y, e1, ay);
        az = fmaf(b1.x, e1, az); aw = fmaf(b1.y, e1, aw);
        ax = fmaf(a2.x, e2, ax); ay = fmaf(a2.y, e2, ay);
        az = fmaf(b2.x, e2, az); aw = fmaf(b2.y, e2, aw);
        ax = fmaf(a3.x, e3, ax); ay = fmaf(a3.y, e3, ay);
        az = fmaf(b3.x, e3, az); aw = fmaf(b3.y, e3, aw);
    }
    for (; t < deg; t++) {
        int2 p = seg[t];
        float e = __int_as_float(p.y);
        ssum += e;
        uint2 rr = *(const uint2*)&g_hh[p.x * 128 + lo];
        float2 f01 = __half22float2(*(__half2*)&rr.x);
        float2 f23 = __half22float2(*(__half2*)&rr.y);
        ax = fmaf(f01.x, e, ax);
        ay = fmaf(f01.y, e, ay);
        az = fmaf(f23.x, e, az);
        aw = fmaf(f23.y, e, aw);
    }

    const float inv = 1.0f / (ssum + EPS_DEN);
    *(float4*)&out[node * 128 + lo] =
        make_float4(ax * inv, ay * inv, az * inv, aw * inv);

    if (lane == 0) g_cursor[node] = 0;   // clean for next graph replay
}

// ---------------------------------------------------------------------------
// Schedule:
//   s1: wvec -> scores -> fill(waits detect) --\
//   s2: detect --------------------------------+
//   s0: gemm_tc ------------------------------- +-> agg
// ---------------------------------------------------------------------------
extern "C" void kernel_launch(void* const* d_in, const int* in_sizes, int n_in,
                              void* d_out, int out_size) {
    const float* x     = (const float*)d_in[0];
    const void*  ei    = d_in[1];
    const float* W     = (const float*)d_in[2];
    const float* att_s = (const float*)d_in[3];
    const float* att_d = (const float*)d_in[4];
    float*       out   = (float*)d_out;

    const int N  = in_sizes[0] / D;
    const int E  = in_sizes[1] / 2;
    const int ET = E + N;

    static cudaStream_t s1 = nullptr, s2 = nullptr;
    static cudaEvent_t evFork = nullptr, evDetect = nullptr, evSide = nullptr;
    if (s1 == nullptr) {
        cudaStreamCreateWithFlags(&s1, cudaStreamNonBlocking);
        cudaStreamCreateWithFlags(&s2, cudaStreamNonBlocking);
        cudaEventCreateWithFlags(&evFork,   cudaEventDisableTiming);
        cudaEventCreateWithFlags(&evDetect, cudaEventDisableTiming);
        cudaEventCreateWithFlags(&evSide,   cudaEventDisableTiming);
    }

    cudaEventRecord(evFork, 0);
    cudaStreamWaitEvent(s1, evFork, 0);
    cudaStreamWaitEvent(s2, evFork, 0);

    // 1) side: w vectors
    k_wvec  <<<(D * 32 + 255) / 256, 256, 0, s1>>>(W, att_s, att_d);
    // 2) dtype detection (parallel, tiny)
    k_detect<<<1, 256, 0, s2>>>(ei, E, N);
    // 3) side: per-node scores
    k_scores<<<(N * 32 + 255) / 256, 256, 0, s1>>>(x, N);
    // 4) main: projection (profiler window lands here)
    {
        dim3 grid((N + 127) / 128, 2);
        k_gemm_tc<<<grid, 256>>>(x, W, N);
    }
    // 5) side: fill (needs scores [s1-serial] + detect [event])
    cudaEventRecord(evDetect, s2);
    cudaStreamWaitEvent(s1, evDetect, 0);
    k_fill<<<(ET + 255) / 256, 256, 0, s1>>>(ei, E, ET, N);
    // 6) join side into main, aggregate
    cudaEventRecord(evSide, s1);
    cudaStreamWaitEvent(0, evSide, 0);
    {
        long long threads = (long long)N * 32;
        int blocks = (int)((threads + 255) / 256);
        k_agg<<<blocks, 256>>>(out, N);
    }
}